// round 5
// baseline (speedup 1.0000x reference)
#include <cuda_runtime.h>

#define NB    8
#define NA    3
#define NH    160
#define NW    160
#define NCLS  80
#define NG    32
#define NPB   (NA*NH*NW)            // 76800
#define NCELL (NB*NPB)              // 614400
#define NBLK  (NCELL/256)           // 2400
#define BLOCKS_PER_BATCH (NPB/256)  // 300

__device__ double       d_loss[4];   // xy, wh, cls, conf (zero-init; reset by last block)
__device__ unsigned int d_count;     // completion counter (reset by last block)

__constant__ float c_anch[9][2] = {
    {10.f,13.f},{16.f,30.f},{33.f,23.f},{30.f,61.f},{62.f,45.f},
    {59.f,119.f},{116.f,90.f},{156.f,198.f},{373.f,326.f}};

__device__ __forceinline__ float sigmoidf_(float x){
    return __fdividef(1.0f, 1.0f + __expf(-x));
}
__device__ __forceinline__ float bcef_(float x, float t){
    return fmaxf(x, 0.0f) - x*t + __logf(1.0f + __expf(-fabsf(x)));
}

__global__ __launch_bounds__(256) void fused_kernel(
    const float* __restrict__ t_bbox, const float* __restrict__ conf,
    const float* __restrict__ cls,    const float* __restrict__ gtb,
    const int*   __restrict__ gcls,   const void* __restrict__ gmask,
    float* __restrict__ out)
{
    __shared__ float4 s_gtc[NG];
    __shared__ float  s_area[NG];
    __shared__ float  s_wred[8];
    __shared__ float  s_am[256];
    __shared__ int    s_ai[256];
    __shared__ int    s_isBool, s_hasgt;

    int tid = threadIdx.x;
    int b   = blockIdx.x / BLOCKS_PER_BATCH;

    // ---------------- GT prep (warp 0): mask dtype sniff + corners ----------------
    if (tid < 32){
        const unsigned char* by = (const unsigned char*)gmask;
        bool non01 = false, off4 = false;
        #pragma unroll
        for (int k = 0; k < 8; k++){
            int idx = tid*8 + k;
            unsigned char v = by[idx];              // first 256 bytes valid for any dtype
            non01 |= (v > 1);
            off4  |= ((idx & 3) != 0) && (v != 0);
        }
        unsigned bNon = __ballot_sync(0xFFFFFFFFu, non01);
        unsigned bOff = __ballot_sync(0xFFFFFFFFu, off4);
        int isBool = (bNon == 0u) && (bOff != 0u);
        if (tid == 0) s_isBool = isBool;

        int g = b*NG + tid;
        bool m = isBool ? (by[g] != 0)
                        : (((const unsigned int*)gmask)[g] != 0u);
        float4 gt = ((const float4*)gtb)[g];
        float4 c; float area;
        if (m){
            c.x = gt.x - 0.5f*gt.z; c.y = gt.y - 0.5f*gt.w;
            c.z = gt.x + 0.5f*gt.z; c.w = gt.y + 0.5f*gt.w;
            area = gt.z*gt.w;
        } else { c = make_float4(0.f,0.f,0.f,0.f); area = 0.f; }
        s_gtc[tid]  = c;
        s_area[tid] = area;
        unsigned ball = __ballot_sync(0xFFFFFFFFu, m);
        if (tid == 0) s_hasgt = (ball != 0u);
    }
    __syncthreads();

    // ---------------- Phase A: cooperative class argmax (4 lanes per cell) --------
    // Warp-LDG touches 8 rows x one 64B-aligned segment = 8 cache lines (vs 32).
    int w   = tid >> 5, l = tid & 31;
    int cg  = l >> 2;          // cell-in-group 0..7
    int sub = l & 3;           // 0..3
    int warpCellBase = blockIdx.x*256 + w*32;
    #pragma unroll
    for (int p = 0; p < 4; p++){
        int cell = warpCellBase + p*8 + cg;
        const float4* cp = (const float4*)(cls + (size_t)cell*NCLS);
        float m = -__int_as_float(0x7f800000);
        int   mi = 0;
        #pragma unroll
        for (int k = 0; k < 5; k++){
            int q = sub + 4*k;          // lanes of a group cover one contiguous 64B
            float4 v = cp[q];
            int c0 = q*4;
            if (v.x > m){ m = v.x; mi = c0;   }
            if (v.y > m){ m = v.y; mi = c0+1; }
            if (v.z > m){ m = v.z; mi = c0+2; }
            if (v.w > m){ m = v.w; mi = c0+3; }
        }
        #pragma unroll
        for (int off = 1; off < 4; off <<= 1){
            float om = __shfl_xor_sync(0xFFFFFFFFu, m,  off);
            int   oi = __shfl_xor_sync(0xFFFFFFFFu, mi, off);
            if (om > m || (om == m && oi < mi)){ m = om; mi = oi; }
        }
        if (sub == 0){ s_am[w*32 + p*8 + cg] = m; s_ai[w*32 + p*8 + cg] = mi; }
    }
    __syncwarp();
    float clsmax = s_am[tid];
    int   clsidx = s_ai[tid];

    // ---------------- Phase B: per-thread decode / IoU / conf loss ----------------
    int cell = blockIdx.x*256 + tid;
    int n = cell - b*NPB;
    int a = n / (NH*NW);
    int r = n - a*(NH*NW);
    int j = r / NW;
    int i = r - j*NW;

    float4 tb = ((const float4*)t_bbox)[cell];
    float sx = sigmoidf_(tb.x), sy = sigmoidf_(tb.y);
    float sw = sigmoidf_(tb.z), sh = sigmoidf_(tb.w);
    float px = (sx*2.f - 0.5f + (float)i)*8.0f;
    float py = (sy*2.f - 0.5f + (float)j)*8.0f;
    float tw = sw*2.f, th = sh*2.f;
    float pw = tw*tw*c_anch[a][0];
    float ph = th*th*c_anch[a][1];

    float cl = conf[cell];
    float score = sigmoidf_(cl) * sigmoidf_(clsmax);

    ((float4*)out)[cell] = make_float4(px, py, pw, ph);
    out[NCELL*4 + cell]  = (float)clsidx;
    out[NCELL*5 + cell]  = score;

    float px1 = px - 0.5f*pw, px2 = px + 0.5f*pw;
    float py1 = py - 0.5f*ph, py2 = py + 0.5f*ph;
    float parea = pw*ph;
    float best = 0.f;
    #pragma unroll 8
    for (int g = 0; g < NG; g++){
        float4 gc = s_gtc[g];
        float iw = fminf(px2, gc.z) - fmaxf(px1, gc.x);
        float ih = fminf(py2, gc.w) - fmaxf(py1, gc.y);
        iw = fmaxf(iw, 0.f); ih = fmaxf(ih, 0.f);
        float inter = iw*ih;
        float uni   = parea + s_area[g] - inter;
        float iou   = __fdividef(inter, uni + 1e-16f);
        best = fmaxf(best, iou);
    }
    float tconf = s_hasgt ? best : 0.f;
    float lc = bcef_(cl, tconf);

    #pragma unroll
    for (int o = 16; o > 0; o >>= 1) lc += __shfl_down_sync(0xFFFFFFFFu, lc, o);
    if (l == 0) s_wred[w] = lc;
    __syncthreads();
    if (tid == 0){
        float s = 0.f;
        #pragma unroll
        for (int k = 0; k < 8; k++) s += s_wred[k];
        atomicAdd(&d_loss[3], (double)s);
    }

    // ---------------- Target losses: 1 warp per GT on blocks 0..31 ----------------
    if (blockIdx.x < 32){
        int gw = blockIdx.x*8 + w;      // 0..255 = b*32+g
        const unsigned char* by = (const unsigned char*)gmask;
        bool m = s_isBool ? (by[gw] != 0)
                          : (((const unsigned int*)gmask)[gw] != 0u);
        if (m){
            float4 gt = ((const float4*)gtb)[gw];   // uniform per warp -> broadcast
            float gwd = gt.z, ghd = gt.w;
            float garea = gwd*ghd;
            float bm = -1.f; int bi = 0;
            #pragma unroll
            for (int k = 0; k < 9; k++){
                float aw = c_anch[k][0], ah = c_anch[k][1];
                float inter = fminf(gwd, aw)*fminf(ghd, ah);
                float uni   = garea + aw*ah - inter;
                float rr    = inter / (uni + 1e-16f);
                if (rr > bm){ bm = rr; bi = k; }
            }
            if (bi < 3){
                int ta = bi;
                int bb = gw >> 5;
                float ux = gt.x*0.125f, uy = gt.y*0.125f;
                int ti = min(max((int)ux, 0), NW-1);
                int tj = min(max((int)uy, 0), NH-1);
                size_t base = ((((size_t)bb*NA + ta)*NH + tj)*NW + ti);
                const float* clp = cls + base*NCLS;

                int gc = gcls[gw];
                float cs = 0.f;
                for (int c = l; c < NCLS; c += 32)
                    cs += bcef_(clp[c], (c == gc) ? 1.f : 0.f);
                #pragma unroll
                for (int o = 16; o > 0; o >>= 1) cs += __shfl_down_sync(0xFFFFFFFFu, cs, o);

                if (l == 0){
                    const float* tbp = t_bbox + base*4;
                    float tgx = (ux - floorf(ux) + 0.5f)*0.5f;
                    float tgy = (uy - floorf(uy) + 0.5f)*0.5f;
                    float tgw = sqrtf(gwd / c_anch[ta][0])*0.5f;
                    float tgh = sqrtf(ghd / c_anch[ta][1])*0.5f;
                    float lxy = bcef_(tbp[0], tgx) + bcef_(tbp[1], tgy);
                    float lwh = bcef_(tbp[2], tgw) + bcef_(tbp[3], tgh);
                    atomicAdd(&d_loss[0], (double)lxy);
                    atomicAdd(&d_loss[1], (double)lwh);
                    atomicAdd(&d_loss[2], (double)(cs * (1.f/NCLS)));
                }
            }
        }
    }

    // ---------------- Finalize: last block writes loss, resets state --------------
    __syncthreads();
    if (tid == 0){
        __threadfence();
        unsigned old = atomicAdd(&d_count, 1u);
        if (old == NBLK - 1u){
            double s = atomicAdd(&d_loss[0], 0.0) + atomicAdd(&d_loss[1], 0.0)
                     + atomicAdd(&d_loss[2], 0.0) + atomicAdd(&d_loss[3], 0.0);
            out[NCELL*6] = (float)(s * (1.0/NB));
            d_loss[0] = 0.0; d_loss[1] = 0.0; d_loss[2] = 0.0; d_loss[3] = 0.0;
            d_count = 0u;
            __threadfence();
        }
    }
}

extern "C" void kernel_launch(void* const* d_in, const int* in_sizes, int n_in,
                              void* d_out, int out_size)
{
    const float* t_bbox = (const float*)d_in[0];
    const float* conf   = (const float*)d_in[1];
    const float* cls    = (const float*)d_in[2];
    const float* gtb    = (const float*)d_in[3];
    const int*   gcls   = (const int*)  d_in[4];
    const void*  gmask  =               d_in[5];
    float* out = (float*)d_out;

    fused_kernel<<<NBLK, 256>>>(t_bbox, conf, cls, gtb, gcls, gmask, out);
}

// round 6
// speedup vs baseline: 1.2761x; 1.2761x over previous
#include <cuda_runtime.h>

#define NB    8
#define NA    3
#define NH    160
#define NW    160
#define NCLS  80
#define NG    32
#define NPB   (NA*NH*NW)            // 76800
#define NCELL (NB*NPB)              // 614400
#define NBLK  (NCELL/256)           // 2400
#define BLOCKS_PER_BATCH (NPB/256)  // 300

__device__ double       d_loss[4];   // xy, wh, cls, conf (zero-init; reset by last block)
__device__ unsigned int d_count;     // completion counter (reset by last block)

__constant__ float c_anch[9][2] = {
    {10.f,13.f},{16.f,30.f},{33.f,23.f},{30.f,61.f},{62.f,45.f},
    {59.f,119.f},{116.f,90.f},{156.f,198.f},{373.f,326.f}};

__device__ __forceinline__ float sigmoidf_(float x){
    return __fdividef(1.0f, 1.0f + __expf(-x));
}
__device__ __forceinline__ float bcef_(float x, float t){
    return fmaxf(x, 0.0f) - x*t + __logf(1.0f + __expf(-fabsf(x)));
}

__global__ __launch_bounds__(256, 6) void fused_kernel(
    const float* __restrict__ t_bbox, const float* __restrict__ conf,
    const float* __restrict__ cls,    const float* __restrict__ gtb,
    const int*   __restrict__ gcls,   const void* __restrict__ gmask,
    float* __restrict__ out)
{
    __shared__ float4 s_gtc[NG];
    __shared__ float  s_area[NG];
    __shared__ float  s_wred[8];
    __shared__ int    s_isBool, s_hasgt;

    int tid = threadIdx.x;
    int b   = blockIdx.x / BLOCKS_PER_BATCH;

    // ---------------- GT prep (warp 0): mask dtype sniff + corners ----------------
    if (tid < 32){
        const unsigned char* by = (const unsigned char*)gmask;
        bool non01 = false, off4 = false;
        #pragma unroll
        for (int k = 0; k < 8; k++){
            int idx = tid*8 + k;
            unsigned char v = by[idx];              // first 256 bytes valid for any dtype
            non01 |= (v > 1);
            off4  |= ((idx & 3) != 0) && (v != 0);
        }
        unsigned bNon = __ballot_sync(0xFFFFFFFFu, non01);
        unsigned bOff = __ballot_sync(0xFFFFFFFFu, off4);
        int isBool = (bNon == 0u) && (bOff != 0u);
        if (tid == 0) s_isBool = isBool;

        int g = b*NG + tid;
        bool m = isBool ? (by[g] != 0)
                        : (((const unsigned int*)gmask)[g] != 0u);
        float4 gt = ((const float4*)gtb)[g];
        float4 c; float area;
        if (m){
            c.x = gt.x - 0.5f*gt.z; c.y = gt.y - 0.5f*gt.w;
            c.z = gt.x + 0.5f*gt.z; c.w = gt.y + 0.5f*gt.w;
            area = gt.z*gt.w;
        } else { c = make_float4(0.f,0.f,0.f,0.f); area = 0.f; }
        s_gtc[tid]  = c;
        s_area[tid] = area;
        unsigned ball = __ballot_sync(0xFFFFFFFFu, m);
        if (tid == 0) s_hasgt = (ball != 0u);
    }
    __syncthreads();

    int w = tid >> 5, l = tid & 31;
    int cell = blockIdx.x*256 + tid;
    int n = cell - b*NPB;
    int a = n / (NH*NW);
    int r = n - a*(NH*NW);
    int j = r / NW;
    int i = r - j*NW;

    // ---- class argmax over 80 logits (per-thread, float4 loads) ----
    const float4* cp = (const float4*)(cls + (size_t)cell*NCLS);
    float m = -__int_as_float(0x7f800000);  // -inf
    int   mi = 0;
    #pragma unroll
    for (int q = 0; q < NCLS/4; q++){
        float4 v = cp[q];
        int c0 = q*4;
        if (v.x > m){ m = v.x; mi = c0;   }
        if (v.y > m){ m = v.y; mi = c0+1; }
        if (v.z > m){ m = v.z; mi = c0+2; }
        if (v.w > m){ m = v.w; mi = c0+3; }
    }

    // ---- decode p_bbox ----
    float4 tb = ((const float4*)t_bbox)[cell];
    float sx = sigmoidf_(tb.x), sy = sigmoidf_(tb.y);
    float sw = sigmoidf_(tb.z), sh = sigmoidf_(tb.w);
    float px = (sx*2.f - 0.5f + (float)i)*8.0f;
    float py = (sy*2.f - 0.5f + (float)j)*8.0f;
    float tw = sw*2.f, th = sh*2.f;
    float pw = tw*tw*c_anch[a][0];
    float ph = th*th*c_anch[a][1];

    float cl = conf[cell];
    float score = sigmoidf_(cl) * sigmoidf_(m);

    ((float4*)out)[cell] = make_float4(px, py, pw, ph);
    out[NCELL*4 + cell]  = (float)mi;
    out[NCELL*5 + cell]  = score;

    // ---- tconf = max IoU over 32 gts ----
    float px1 = px - 0.5f*pw, px2 = px + 0.5f*pw;
    float py1 = py - 0.5f*ph, py2 = py + 0.5f*ph;
    float parea = pw*ph;
    float best = 0.f;
    #pragma unroll 8
    for (int g = 0; g < NG; g++){
        float4 gc = s_gtc[g];
        float iw = fminf(px2, gc.z) - fmaxf(px1, gc.x);
        float ih = fminf(py2, gc.w) - fmaxf(py1, gc.y);
        iw = fmaxf(iw, 0.f); ih = fmaxf(ih, 0.f);
        float inter = iw*ih;
        float uni   = parea + s_area[g] - inter;
        float iou   = __fdividef(inter, uni + 1e-16f);
        best = fmaxf(best, iou);
    }
    float tconf = s_hasgt ? best : 0.f;
    float lc = bcef_(cl, tconf);

    #pragma unroll
    for (int o = 16; o > 0; o >>= 1) lc += __shfl_down_sync(0xFFFFFFFFu, lc, o);
    if (l == 0) s_wred[w] = lc;
    __syncthreads();
    if (tid == 0){
        float s = 0.f;
        #pragma unroll
        for (int k = 0; k < 8; k++) s += s_wred[k];
        atomicAdd(&d_loss[3], (double)s);
    }

    // ---------------- Target losses: 1 warp per GT on blocks 0..31 ----------------
    if (blockIdx.x < 32){
        int gw = blockIdx.x*8 + w;      // 0..255 = b*32+g
        const unsigned char* by = (const unsigned char*)gmask;
        bool mk = s_isBool ? (by[gw] != 0)
                           : (((const unsigned int*)gmask)[gw] != 0u);
        if (mk){
            float4 gt = ((const float4*)gtb)[gw];   // uniform per warp -> broadcast
            float gwd = gt.z, ghd = gt.w;
            float garea = gwd*ghd;
            float bm = -1.f; int bi = 0;
            #pragma unroll
            for (int k = 0; k < 9; k++){
                float aw = c_anch[k][0], ah = c_anch[k][1];
                float inter = fminf(gwd, aw)*fminf(ghd, ah);
                float uni   = garea + aw*ah - inter;
                float rr    = inter / (uni + 1e-16f);
                if (rr > bm){ bm = rr; bi = k; }
            }
            if (bi < 3){
                int ta = bi;
                int bb = gw >> 5;
                float ux = gt.x*0.125f, uy = gt.y*0.125f;
                int ti = min(max((int)ux, 0), NW-1);
                int tj = min(max((int)uy, 0), NH-1);
                size_t base = ((((size_t)bb*NA + ta)*NH + tj)*NW + ti);
                const float* clp = cls + base*NCLS;

                int gc = gcls[gw];
                float cs = 0.f;
                for (int c = l; c < NCLS; c += 32)
                    cs += bcef_(clp[c], (c == gc) ? 1.f : 0.f);
                #pragma unroll
                for (int o = 16; o > 0; o >>= 1) cs += __shfl_down_sync(0xFFFFFFFFu, cs, o);

                if (l == 0){
                    const float* tbp = t_bbox + base*4;
                    float tgx = (ux - floorf(ux) + 0.5f)*0.5f;
                    float tgy = (uy - floorf(uy) + 0.5f)*0.5f;
                    float tgw = sqrtf(gwd / c_anch[ta][0])*0.5f;
                    float tgh = sqrtf(ghd / c_anch[ta][1])*0.5f;
                    float lxy = bcef_(tbp[0], tgx) + bcef_(tbp[1], tgy);
                    float lwh = bcef_(tbp[2], tgw) + bcef_(tbp[3], tgh);
                    atomicAdd(&d_loss[0], (double)lxy);
                    atomicAdd(&d_loss[1], (double)lwh);
                    atomicAdd(&d_loss[2], (double)(cs * (1.f/NCLS)));
                }
            }
        }
    }

    // ---------------- Finalize: last block writes loss, resets state --------------
    __syncthreads();
    if (tid == 0){
        __threadfence();
        unsigned old = atomicAdd(&d_count, 1u);
        if (old == NBLK - 1u){
            double s = atomicAdd(&d_loss[0], 0.0) + atomicAdd(&d_loss[1], 0.0)
                     + atomicAdd(&d_loss[2], 0.0) + atomicAdd(&d_loss[3], 0.0);
            out[NCELL*6] = (float)(s * (1.0/NB));
            d_loss[0] = 0.0; d_loss[1] = 0.0; d_loss[2] = 0.0; d_loss[3] = 0.0;
            d_count = 0u;
            __threadfence();
        }
    }
}

extern "C" void kernel_launch(void* const* d_in, const int* in_sizes, int n_in,
                              void* d_out, int out_size)
{
    const float* t_bbox = (const float*)d_in[0];
    const float* conf   = (const float*)d_in[1];
    const float* cls    = (const float*)d_in[2];
    const float* gtb    = (const float*)d_in[3];
    const int*   gcls   = (const int*)  d_in[4];
    const void*  gmask  =               d_in[5];
    float* out = (float*)d_out;

    fused_kernel<<<NBLK, 256>>>(t_bbox, conf, cls, gtb, gcls, gmask, out);
}